// round 15
// baseline (speedup 1.0000x reference)
#include <cuda_runtime.h>
#include <cuda_fp16.h>
#include <cstdint>

#define D 128
#define MAX_N 50000
#define MAX_N_PAD 50176          // padded: GEMM tiles may over-read safely
#define EDGES_PER_WARP 64
#define GDEPTH 8                 // cp.async gather pipeline depth (per warp)

// ===========================================================================
// Static scratch (no allocations allowed)
// ===========================================================================
__device__ __align__(256) __half g_in_h[(size_t)MAX_N * D];       // fp16 input
__device__ __align__(256) __half g_W_h[D * D];                    // fp16 W
__device__ __align__(256) __half g_agg_h[(size_t)MAX_N_PAD * D];  // fp16 agg
__device__ __align__(256) float g_deg[MAX_N];                     // rowsum(adj_val)

// ---- cp.async helpers ----
__device__ __forceinline__ uint32_t smem_u32(const void* p) {
    return (uint32_t)__cvta_generic_to_shared(p);
}
__device__ __forceinline__ void cp8(uint32_t dst, const void* src) {
    asm volatile("cp.async.ca.shared.global [%0], [%1], 8;" :: "r"(dst), "l"(src));
}
__device__ __forceinline__ void cp16(uint32_t dst, const void* src) {
    asm volatile("cp.async.cg.shared.global [%0], [%1], 16;" :: "r"(dst), "l"(src));
}
__device__ __forceinline__ void cp_commit() {
    asm volatile("cp.async.commit_group;");
}
template <int NWAIT>
__device__ __forceinline__ void cp_wait() {
    asm volatile("cp.async.wait_group %0;" :: "n"(NWAIT));
}

// ===========================================================================
// Kernel 0: fused prep — convert input/W to fp16 AND zero agg/deg.
// (round-6 winner, verbatim)
// ===========================================================================
__global__ __launch_bounds__(256) void prep_kernel(
    const float* __restrict__ input,
    const float* __restrict__ W,
    __half* __restrict__ in_h,
    __half* __restrict__ W_h,
    __half* __restrict__ agg,
    float* __restrict__ deg,
    int nInPairs, int nWPairs, int nZero16, int nDeg4)
{
    const int i = blockIdx.x * blockDim.x + threadIdx.x;

    if (i < nInPairs) {
        const float4 v0 = reinterpret_cast<const float4*>(input)[i * 2];
        const float4 v1 = reinterpret_cast<const float4*>(input)[i * 2 + 1];
        __half2 h0 = __floats2half2_rn(v0.x, v0.y);
        __half2 h1 = __floats2half2_rn(v0.z, v0.w);
        __half2 h2 = __floats2half2_rn(v1.x, v1.y);
        __half2 h3 = __floats2half2_rn(v1.z, v1.w);
        uint4 u;
        u.x = *reinterpret_cast<uint32_t*>(&h0);
        u.y = *reinterpret_cast<uint32_t*>(&h1);
        u.z = *reinterpret_cast<uint32_t*>(&h2);
        u.w = *reinterpret_cast<uint32_t*>(&h3);
        reinterpret_cast<uint4*>(in_h)[i] = u;
        return;
    }
    int j = i - nInPairs;
    if (j < nWPairs) {
        const float4 v0 = reinterpret_cast<const float4*>(W)[j * 2];
        const float4 v1 = reinterpret_cast<const float4*>(W)[j * 2 + 1];
        __half2 h0 = __floats2half2_rn(v0.x, v0.y);
        __half2 h1 = __floats2half2_rn(v0.z, v0.w);
        __half2 h2 = __floats2half2_rn(v1.x, v1.y);
        __half2 h3 = __floats2half2_rn(v1.z, v1.w);
        uint4 u;
        u.x = *reinterpret_cast<uint32_t*>(&h0);
        u.y = *reinterpret_cast<uint32_t*>(&h1);
        u.z = *reinterpret_cast<uint32_t*>(&h2);
        u.w = *reinterpret_cast<uint32_t*>(&h3);
        reinterpret_cast<uint4*>(W_h)[j] = u;
        return;
    }
    j -= nWPairs;
    if (j < nZero16) {
        reinterpret_cast<uint4*>(agg)[j] = make_uint4(0, 0, 0, 0);
        return;
    }
    j -= nZero16;
    if (j < nDeg4)
        reinterpret_cast<uint4*>(deg)[j] = make_uint4(0, 0, 0, 0);
}

// ===========================================================================
// Kernel 1: COO scatter, cp.async-pipelined gather (MLP 8 per warp).
// Round-6 consume order/flush logic verbatim; only the gather mechanism
// changes: edge j+8's row is cp.async'd into an 8-slot smem ring while
// edge j is consumed from smem. Per-thread wait_group<7> makes a lane's
// own 8B visible to itself; no cross-lane smem reads -> no syncwarp.
// ===========================================================================
__device__ __forceinline__ void flush_row(__half* __restrict__ agg,
                                          float* __restrict__ deg,
                                          int curRow, int lane,
                                          const float4& acc, float degAcc,
                                          int firstRow, bool isFinal)
{
    if (curRow < 0) return;
    __half2 h0 = __floats2half2_rn(acc.x, acc.y);
    __half2 h1 = __floats2half2_rn(acc.z, acc.w);
    __half2* p = reinterpret_cast<__half2*>(agg + (size_t)curRow * D + lane * 4);
    if (curRow == firstRow || isFinal) {
        atomicAdd(p + 0, h0);
        atomicAdd(p + 1, h1);
        if (lane == 0) atomicAdd(&deg[curRow], degAcc);
    } else {
        uint2 u = make_uint2(*reinterpret_cast<uint32_t*>(&h0),
                             *reinterpret_cast<uint32_t*>(&h1));
        *reinterpret_cast<uint2*>(p) = u;
        if (lane == 0) deg[curRow] = degAcc;
    }
}

__global__ __launch_bounds__(256) void scatter_kernel(
    const int* __restrict__ adj_row,
    const int* __restrict__ adj_col,
    const float* __restrict__ adj_val,
    const __half* __restrict__ in_h,
    __half* __restrict__ agg,
    float* __restrict__ deg,
    int E)
{
    extern __shared__ char ssc[];   // 8 warps x GDEPTH x 256B = 16 KB
    const int warpId = (blockIdx.x * blockDim.x + threadIdx.x) >> 5;
    const int lane = threadIdx.x & 31;
    const int base = warpId * EDGES_PER_WARP;
    if (base >= E) return;

    char* wbase = ssc + (size_t)(threadIdx.x >> 5) * (GDEPTH * 256);
    const uint32_t waddr = smem_u32(wbase) + (uint32_t)lane * 8;

    // Preload this warp's 64 edges (two 32-edge register chunks)
    int rr[2] = {-2, -2}, cc[2] = {0, 0};
    float vv[2] = {0.f, 0.f};
    #pragma unroll
    for (int t = 0; t < 2; ++t) {
        const int e = base + t * 32 + lane;
        if (e < E) { rr[t] = adj_row[e]; cc[t] = adj_col[e]; vv[t] = adj_val[e]; }
    }

    // ---- Prologue: issue gathers for edges 0..7 (one commit group each) ----
    #pragma unroll
    for (int p = 0; p < GDEPTH; ++p) {
        const int rp = __shfl_sync(0xFFFFFFFFu, rr[0], p);
        const int cp_ = __shfl_sync(0xFFFFFFFFu, cc[0], p);
        if (rp >= 0)
            cp8(waddr + (uint32_t)p * 256,
                in_h + (size_t)cp_ * D + lane * 4);
        cp_commit();   // empty group if invalid: keeps FIFO aligned
    }

    const int firstRow = __shfl_sync(0xFFFFFFFFu, rr[0], 0);
    int curRow = -1;
    float4 acc = make_float4(0.f, 0.f, 0.f, 0.f);
    float degAcc = 0.f;

    // ---- Main loop: consume edge j, issue edge j+8 ----
    for (int j = 0; j < EDGES_PER_WARP; ++j) {
        const int half = j >> 5, sl = j & 31;
        const int rj = __shfl_sync(0xFFFFFFFFu, rr[half], sl);
        if (rj < 0) break;                       // uniform: trailing edges only
        const float vj = __shfl_sync(0xFFFFFFFFu, vv[half], sl);

        cp_wait<GDEPTH - 1>();                   // group j complete (per-thread)

        if (rj != curRow) {
            flush_row(agg, deg, curRow, lane, acc, degAcc, firstRow, false);
            curRow = rj;
            acc = make_float4(0.f, 0.f, 0.f, 0.f);
            degAcc = 0.f;
        }
        const uint2 sv = *reinterpret_cast<const uint2*>(
            wbase + (size_t)(j & (GDEPTH - 1)) * 256 + (size_t)lane * 8);
        const float2 f0 = __half22float2(*reinterpret_cast<const __half2*>(&sv.x));
        const float2 f1 = __half22float2(*reinterpret_cast<const __half2*>(&sv.y));
        acc.x += vj * f0.x;
        acc.y += vj * f0.y;
        acc.z += vj * f1.x;
        acc.w += vj * f1.y;
        degAcc += vj;

        // Issue gather for edge j+GDEPTH
        const int jn = j + GDEPTH;
        if (jn < EDGES_PER_WARP) {
            const int rn = __shfl_sync(0xFFFFFFFFu, rr[jn >> 5], jn & 31);
            const int cn = __shfl_sync(0xFFFFFFFFu, cc[jn >> 5], jn & 31);
            if (rn >= 0)
                cp8(waddr + (uint32_t)(jn & (GDEPTH - 1)) * 256,
                    in_h + (size_t)cn * D + lane * 4);
        }
        cp_commit();
    }
    cp_wait<0>();    // drain any outstanding groups
    flush_row(agg, deg, curRow, lane, acc, degAcc, firstRow, true);
}

// ===========================================================================
// mma.sync / ldmatrix helpers
// ===========================================================================
__device__ __forceinline__ void ldmx4(uint32_t& r0, uint32_t& r1,
                                      uint32_t& r2, uint32_t& r3,
                                      uint32_t saddr)
{
    asm volatile("ldmatrix.sync.aligned.m8n8.x4.shared.b16 {%0,%1,%2,%3}, [%4];"
                 : "=r"(r0), "=r"(r1), "=r"(r2), "=r"(r3) : "r"(saddr));
}
__device__ __forceinline__ void mma_f16(float& c0, float& c1, float& c2, float& c3,
                                        uint32_t a0, uint32_t a1, uint32_t a2, uint32_t a3,
                                        uint32_t b0, uint32_t b1)
{
    asm volatile(
        "mma.sync.aligned.m16n8k16.row.col.f32.f16.f16.f32 "
        "{%0,%1,%2,%3}, {%4,%5,%6,%7}, {%8,%9}, {%0,%1,%2,%3};"
        : "+f"(c0), "+f"(c1), "+f"(c2), "+f"(c3)
        : "r"(a0), "r"(a1), "r"(a2), "r"(a3), "r"(b0), "r"(b1));
}

// ===========================================================================
// Kernel 2: persistent fp16 tensor-core GEMM + fused epilogue.
// (round-13 winner, verbatim: grid = min(nTiles, 2*SMs))
// ===========================================================================
#define LDH 136
#define TILE_BYTES_H (128 * LDH * 2)
#define SM_BV 0
#define SM_B  1024
#define SM_A0 (SM_B + TILE_BYTES_H)
#define SM_A1 (SM_A0 + TILE_BYTES_H)
#define GEMM_SMEM_TOTAL (SM_A1 + TILE_BYTES_H)   // 105472 B

struct GemmCtx {
    const float* deg;
    float* out;
    const float* sb;
    int N, wm, wn, lane;
    uint32_t sB;
};

__device__ __forceinline__ void compute_tile(const GemmCtx& ctx, uint32_t sA,
                                             int rowBase)
{
    float acc[2][8][4];
    #pragma unroll
    for (int mi = 0; mi < 2; ++mi)
        #pragma unroll
        for (int ni = 0; ni < 8; ++ni)
            #pragma unroll
            for (int q = 0; q < 4; ++q)
                acc[mi][ni][q] = 0.f;

    const int lrow = ctx.lane & 15;
    const int lkof = (ctx.lane >> 4) << 3;

    #pragma unroll
    for (int ks = 0; ks < 8; ++ks) {
        const uint32_t kb = (uint32_t)(ks * 16 + lkof) * 2;

        uint32_t a[2][4];
        #pragma unroll
        for (int mi = 0; mi < 2; ++mi) {
            uint32_t ra = (uint32_t)((ctx.wm * 32 + mi * 16 + lrow) * LDH) * 2 + kb;
            ldmx4(a[mi][0], a[mi][1], a[mi][2], a[mi][3], sA + ra);
        }
        uint32_t bf[4][4];
        #pragma unroll
        for (int nb = 0; nb < 4; ++nb) {
            uint32_t rb = (uint32_t)((ctx.wn * 64 + nb * 16 + lrow) * LDH) * 2 + kb;
            ldmx4(bf[nb][0], bf[nb][1], bf[nb][2], bf[nb][3], ctx.sB + rb);
        }
        #pragma unroll
        for (int mi = 0; mi < 2; ++mi) {
            #pragma unroll
            for (int nb = 0; nb < 4; ++nb) {
                mma_f16(acc[mi][nb*2][0], acc[mi][nb*2][1], acc[mi][nb*2][2], acc[mi][nb*2][3],
                        a[mi][0], a[mi][1], a[mi][2], a[mi][3], bf[nb][0], bf[nb][2]);
                mma_f16(acc[mi][nb*2+1][0], acc[mi][nb*2+1][1], acc[mi][nb*2+1][2], acc[mi][nb*2+1][3],
                        a[mi][0], a[mi][1], a[mi][2], a[mi][3], bf[nb][1], bf[nb][3]);
            }
        }
    }

    const int qrow = ctx.lane >> 2;
    const int qcol = (ctx.lane & 3) << 1;

    #pragma unroll
    for (int mi = 0; mi < 2; ++mi) {
        const int r0 = rowBase + ctx.wm * 32 + mi * 16 + qrow;
        const int r1 = r0 + 8;
        const float d0 = (r0 < ctx.N) ? ctx.deg[r0] : 0.f;
        const float d1 = (r1 < ctx.N) ? ctx.deg[r1] : 0.f;
        #pragma unroll
        for (int ni = 0; ni < 8; ++ni) {
            const int c = ctx.wn * 64 + ni * 8 + qcol;
            const float b0v = ctx.sb[c], b1v = ctx.sb[c + 1];
            if (r0 < ctx.N) {
                float2 o;
                o.x = tanhf(acc[mi][ni][0] + d0 * b0v);
                o.y = tanhf(acc[mi][ni][1] + d0 * b1v);
                *reinterpret_cast<float2*>(&ctx.out[(size_t)r0 * D + c]) = o;
            }
            if (r1 < ctx.N) {
                float2 o;
                o.x = tanhf(acc[mi][ni][2] + d1 * b0v);
                o.y = tanhf(acc[mi][ni][3] + d1 * b1v);
                *reinterpret_cast<float2*>(&ctx.out[(size_t)r1 * D + c]) = o;
            }
        }
    }
}

__global__ __launch_bounds__(256, 2) void gemm_mma_kernel(
    const __half* __restrict__ agg,
    const __half* __restrict__ W_h,
    const float* __restrict__ b,
    const float* __restrict__ deg,
    float* __restrict__ out,
    int N, int nTiles)
{
    extern __shared__ char smem[];
    float* sb = reinterpret_cast<float*>(smem + SM_BV);

    const int tid  = threadIdx.x;
    const int wid  = tid >> 5;
    const int lane = tid & 31;

    const int tile0 = blockIdx.x;
    const int tile1 = blockIdx.x + gridDim.x;
    const int rowBase0 = tile0 * 128;
    const int rowBase1 = tile1 * 128;

    if (tid < 128) sb[tid] = b[tid];

    const uint32_t sB  = smem_u32(smem + SM_B);
    const uint32_t sA0 = smem_u32(smem + SM_A0);
    const uint32_t sA1 = smem_u32(smem + SM_A1);

    #pragma unroll
    for (int it = 0; it < 8; ++it) {
        const int i = tid + it * 256;
        const int r = i >> 4;
        const int c = i & 15;
        cp16(sB  + r * (LDH * 2) + c * 16, W_h + (size_t)r * D + c * 8);
        cp16(sA0 + r * (LDH * 2) + c * 16,
             agg + (size_t)(rowBase0 + r) * D + c * 8);
    }
    cp_commit();

    if (tile1 < nTiles) {
        #pragma unroll
        for (int it = 0; it < 8; ++it) {
            const int i = tid + it * 256;
            const int r = i >> 4;
            const int c = i & 15;
            cp16(sA1 + r * (LDH * 2) + c * 16,
                 agg + (size_t)(rowBase1 + r) * D + c * 8);
        }
    }
    cp_commit();   // group committed even if empty: keeps wait<1> semantics

    GemmCtx ctx;
    ctx.deg = deg; ctx.out = out; ctx.sb = sb; ctx.N = N;
    ctx.wm = wid & 3; ctx.wn = wid >> 2; ctx.lane = lane; ctx.sB = sB;

    cp_wait<1>();
    __syncthreads();
    compute_tile(ctx, sA0, rowBase0);

    if (tile1 < nTiles) {
        cp_wait<0>();
        __syncthreads();
        compute_tile(ctx, sA1, rowBase1);
    }
}

// ===========================================================================
extern "C" void kernel_launch(void* const* d_in, const int* in_sizes, int n_in,
                              void* d_out, int out_size)
{
    const float* input   = (const float*)d_in[0];
    const float* W       = (const float*)d_in[1];
    const float* b       = (const float*)d_in[2];
    const int*   adj_row = (const int*)d_in[3];
    const int*   adj_col = (const int*)d_in[4];
    const float* adj_val = (const float*)d_in[5];
    float* out = (float*)d_out;

    const int N = in_sizes[0] / D;
    const int E = in_sizes[3];

    __half *inhPtr = nullptr, *whPtr = nullptr, *agghPtr = nullptr;
    float *degPtr = nullptr;
    cudaGetSymbolAddress((void**)&inhPtr, g_in_h);
    cudaGetSymbolAddress((void**)&whPtr, g_W_h);
    cudaGetSymbolAddress((void**)&agghPtr, g_agg_h);
    cudaGetSymbolAddress((void**)&degPtr, g_deg);

    // Fused prep: convert input/W to fp16 + zero agg/deg (round-6 shape)
    const int nInPairs = N * D / 8;
    const int nWPairs  = D * D / 8;
    const int nZero16  = N * D / 8;
    const int nDeg4    = (N + 3) / 4;
    const int totalPrep = nInPairs + nWPairs + nZero16 + nDeg4;
    prep_kernel<<<(totalPrep + 255) / 256, 256>>>(
        input, W, inhPtr, whPtr, agghPtr, degPtr,
        nInPairs, nWPairs, nZero16, nDeg4);

    // cp.async-pipelined scatter (16 KB dynamic smem ring per block)
    const int nWarps = (E + EDGES_PER_WARP - 1) / EDGES_PER_WARP;
    const int scatterBlocks = (nWarps * 32 + 255) / 256;
    const int scSmem = 8 * GDEPTH * 256;   // 16384 B
    scatter_kernel<<<scatterBlocks, 256, scSmem>>>(
        adj_row, adj_col, adj_val, inhPtr, agghPtr, degPtr, E);

    // Persistent tensor-core GEMM + fused bias/tanh epilogue (round-13)
    cudaFuncSetAttribute(gemm_mma_kernel,
                         cudaFuncAttributeMaxDynamicSharedMemorySize,
                         GEMM_SMEM_TOTAL);
    int sms = 148;
    cudaDeviceGetAttribute(&sms, cudaDevAttrMultiProcessorCount, 0);
    const int nTiles = (N + 127) / 128;
    int gemmBlocks = 2 * sms;
    if (gemmBlocks > nTiles) gemmBlocks = nTiles;
    gemm_mma_kernel<<<gemmBlocks, 256, GEMM_SMEM_TOTAL>>>(
        agghPtr, whPtr, b, degPtr, out, N, nTiles);
}

// round 16
// speedup vs baseline: 1.0331x; 1.0331x over previous
#include <cuda_runtime.h>
#include <cuda_fp16.h>
#include <cstdint>

#define D 128
#define MAX_N 50000
#define MAX_N_PAD 50176          // padded: GEMM tiles may over-read safely
#define EDGES_PER_WARP 64

// ===========================================================================
// Static scratch (no allocations allowed)
// ===========================================================================
__device__ __align__(256) __half g_in_h[(size_t)MAX_N * D];       // fp16 input
__device__ __align__(256) __half g_W_h[D * D];                    // fp16 W
__device__ __align__(256) __half g_agg_h[(size_t)MAX_N_PAD * D];  // fp16 agg
__device__ __align__(256) float g_deg[MAX_N];                     // rowsum(adj_val)

// Single-instruction tanh (MUFU.TANH, sm_75+ baseline feature)
__device__ __forceinline__ float tanh_fast(float x) {
    float y;
    asm("tanh.approx.f32 %0, %1;" : "=f"(y) : "f"(x));
    return y;
}

// ===========================================================================
// Kernel 0: fused prep — convert input/W to fp16 AND zero agg/deg.
// (round-6 winner, verbatim)
// ===========================================================================
__global__ __launch_bounds__(256) void prep_kernel(
    const float* __restrict__ input,
    const float* __restrict__ W,
    __half* __restrict__ in_h,
    __half* __restrict__ W_h,
    __half* __restrict__ agg,
    float* __restrict__ deg,
    int nInPairs, int nWPairs, int nZero16, int nDeg4)
{
    const int i = blockIdx.x * blockDim.x + threadIdx.x;

    if (i < nInPairs) {
        const float4 v0 = reinterpret_cast<const float4*>(input)[i * 2];
        const float4 v1 = reinterpret_cast<const float4*>(input)[i * 2 + 1];
        __half2 h0 = __floats2half2_rn(v0.x, v0.y);
        __half2 h1 = __floats2half2_rn(v0.z, v0.w);
        __half2 h2 = __floats2half2_rn(v1.x, v1.y);
        __half2 h3 = __floats2half2_rn(v1.z, v1.w);
        uint4 u;
        u.x = *reinterpret_cast<uint32_t*>(&h0);
        u.y = *reinterpret_cast<uint32_t*>(&h1);
        u.z = *reinterpret_cast<uint32_t*>(&h2);
        u.w = *reinterpret_cast<uint32_t*>(&h3);
        reinterpret_cast<uint4*>(in_h)[i] = u;
        return;
    }
    int j = i - nInPairs;
    if (j < nWPairs) {
        const float4 v0 = reinterpret_cast<const float4*>(W)[j * 2];
        const float4 v1 = reinterpret_cast<const float4*>(W)[j * 2 + 1];
        __half2 h0 = __floats2half2_rn(v0.x, v0.y);
        __half2 h1 = __floats2half2_rn(v0.z, v0.w);
        __half2 h2 = __floats2half2_rn(v1.x, v1.y);
        __half2 h3 = __floats2half2_rn(v1.z, v1.w);
        uint4 u;
        u.x = *reinterpret_cast<uint32_t*>(&h0);
        u.y = *reinterpret_cast<uint32_t*>(&h1);
        u.z = *reinterpret_cast<uint32_t*>(&h2);
        u.w = *reinterpret_cast<uint32_t*>(&h3);
        reinterpret_cast<uint4*>(W_h)[j] = u;
        return;
    }
    j -= nWPairs;
    if (j < nZero16) {
        reinterpret_cast<uint4*>(agg)[j] = make_uint4(0, 0, 0, 0);
        return;
    }
    j -= nZero16;
    if (j < nDeg4)
        reinterpret_cast<uint4*>(deg)[j] = make_uint4(0, 0, 0, 0);
}

// ===========================================================================
// Kernel 1: COO scatter on fp16 input, fp32 register accumulation:
//   g_agg_h[r] += val * in_h[c]  (fp16 store),  g_deg[r] += val
// (round-6 winner, verbatim)
// ===========================================================================
__device__ __forceinline__ void flush_row(__half* __restrict__ agg,
                                          float* __restrict__ deg,
                                          int curRow, int lane,
                                          const float4& acc, float degAcc,
                                          int firstRow, bool isFinal)
{
    if (curRow < 0) return;
    __half2 h0 = __floats2half2_rn(acc.x, acc.y);
    __half2 h1 = __floats2half2_rn(acc.z, acc.w);
    __half2* p = reinterpret_cast<__half2*>(agg + (size_t)curRow * D + lane * 4);
    if (curRow == firstRow || isFinal) {
        atomicAdd(p + 0, h0);
        atomicAdd(p + 1, h1);
        if (lane == 0) atomicAdd(&deg[curRow], degAcc);
    } else {
        uint2 u = make_uint2(*reinterpret_cast<uint32_t*>(&h0),
                             *reinterpret_cast<uint32_t*>(&h1));
        *reinterpret_cast<uint2*>(p) = u;
        if (lane == 0) deg[curRow] = degAcc;
    }
}

__global__ __launch_bounds__(256) void scatter_kernel(
    const int* __restrict__ adj_row,
    const int* __restrict__ adj_col,
    const float* __restrict__ adj_val,
    const __half* __restrict__ in_h,
    __half* __restrict__ agg,
    float* __restrict__ deg,
    int E)
{
    const int warpId = (blockIdx.x * blockDim.x + threadIdx.x) >> 5;
    const int lane = threadIdx.x & 31;
    const int base = warpId * EDGES_PER_WARP;
    if (base >= E) return;

    const int firstRow = adj_row[base];
    int curRow = -1;
    float4 acc = make_float4(0.f, 0.f, 0.f, 0.f);
    float degAcc = 0.f;

    for (int t = 0; t < EDGES_PER_WARP; t += 32) {
        const int e = base + t + lane;
        int r = -2, c = 0;
        float v = 0.f;
        if (e < E) { r = adj_row[e]; c = adj_col[e]; v = adj_val[e]; }

        #pragma unroll
        for (int j = 0; j < 32; ++j) {
            const int   rj = __shfl_sync(0xFFFFFFFFu, r, j);
            const int   cj = __shfl_sync(0xFFFFFFFFu, c, j);
            const float vj = __shfl_sync(0xFFFFFFFFu, v, j);
            if (rj < 0) break;
            if (rj != curRow) {
                flush_row(agg, deg, curRow, lane, acc, degAcc, firstRow, false);
                curRow = rj;
                acc = make_float4(0.f, 0.f, 0.f, 0.f);
                degAcc = 0.f;
            }
            const uint2 sv = *reinterpret_cast<const uint2*>(
                in_h + (size_t)cj * D + lane * 4);
            const float2 f0 = __half22float2(*reinterpret_cast<const __half2*>(&sv.x));
            const float2 f1 = __half22float2(*reinterpret_cast<const __half2*>(&sv.y));
            acc.x += vj * f0.x;
            acc.y += vj * f0.y;
            acc.z += vj * f1.x;
            acc.w += vj * f1.y;
            degAcc += vj;
        }
    }
    flush_row(agg, deg, curRow, lane, acc, degAcc, firstRow, true);
}

// ===========================================================================
// mma.sync / ldmatrix / cp.async helpers
// ===========================================================================
__device__ __forceinline__ void ldmx4(uint32_t& r0, uint32_t& r1,
                                      uint32_t& r2, uint32_t& r3,
                                      uint32_t saddr)
{
    asm volatile("ldmatrix.sync.aligned.m8n8.x4.shared.b16 {%0,%1,%2,%3}, [%4];"
                 : "=r"(r0), "=r"(r1), "=r"(r2), "=r"(r3) : "r"(saddr));
}
__device__ __forceinline__ void mma_f16(float& c0, float& c1, float& c2, float& c3,
                                        uint32_t a0, uint32_t a1, uint32_t a2, uint32_t a3,
                                        uint32_t b0, uint32_t b1)
{
    asm volatile(
        "mma.sync.aligned.m16n8k16.row.col.f32.f16.f16.f32 "
        "{%0,%1,%2,%3}, {%4,%5,%6,%7}, {%8,%9}, {%0,%1,%2,%3};"
        : "+f"(c0), "+f"(c1), "+f"(c2), "+f"(c3)
        : "r"(a0), "r"(a1), "r"(a2), "r"(a3), "r"(b0), "r"(b1));
}
__device__ __forceinline__ uint32_t smem_u32(const void* p) {
    return (uint32_t)__cvta_generic_to_shared(p);
}
__device__ __forceinline__ void cp16(uint32_t dst, const void* src) {
    asm volatile("cp.async.cg.shared.global [%0], [%1], 16;" :: "r"(dst), "l"(src));
}
__device__ __forceinline__ void cp_commit() {
    asm volatile("cp.async.commit_group;");
}
template <int NWAIT>
__device__ __forceinline__ void cp_wait() {
    asm volatile("cp.async.wait_group %0;" :: "n"(NWAIT));
}

// ===========================================================================
// Kernel 2: persistent fp16 tensor-core GEMM + fused epilogue.
// (round-13 structure; ROUND-16 CHANGE: tanhf -> tanh.approx.f32 MUFU)
// ===========================================================================
#define LDH 136
#define TILE_BYTES_H (128 * LDH * 2)
#define SM_BV 0
#define SM_B  1024
#define SM_A0 (SM_B + TILE_BYTES_H)
#define SM_A1 (SM_A0 + TILE_BYTES_H)
#define GEMM_SMEM_TOTAL (SM_A1 + TILE_BYTES_H)   // 105472 B

struct GemmCtx {
    const float* deg;
    float* out;
    const float* sb;
    int N, wm, wn, lane;
    uint32_t sB;
};

__device__ __forceinline__ void compute_tile(const GemmCtx& ctx, uint32_t sA,
                                             int rowBase)
{
    float acc[2][8][4];
    #pragma unroll
    for (int mi = 0; mi < 2; ++mi)
        #pragma unroll
        for (int ni = 0; ni < 8; ++ni)
            #pragma unroll
            for (int q = 0; q < 4; ++q)
                acc[mi][ni][q] = 0.f;

    const int lrow = ctx.lane & 15;
    const int lkof = (ctx.lane >> 4) << 3;

    #pragma unroll
    for (int ks = 0; ks < 8; ++ks) {
        const uint32_t kb = (uint32_t)(ks * 16 + lkof) * 2;

        uint32_t a[2][4];
        #pragma unroll
        for (int mi = 0; mi < 2; ++mi) {
            uint32_t ra = (uint32_t)((ctx.wm * 32 + mi * 16 + lrow) * LDH) * 2 + kb;
            ldmx4(a[mi][0], a[mi][1], a[mi][2], a[mi][3], sA + ra);
        }
        uint32_t bf[4][4];
        #pragma unroll
        for (int nb = 0; nb < 4; ++nb) {
            uint32_t rb = (uint32_t)((ctx.wn * 64 + nb * 16 + lrow) * LDH) * 2 + kb;
            ldmx4(bf[nb][0], bf[nb][1], bf[nb][2], bf[nb][3], ctx.sB + rb);
        }
        #pragma unroll
        for (int mi = 0; mi < 2; ++mi) {
            #pragma unroll
            for (int nb = 0; nb < 4; ++nb) {
                mma_f16(acc[mi][nb*2][0], acc[mi][nb*2][1], acc[mi][nb*2][2], acc[mi][nb*2][3],
                        a[mi][0], a[mi][1], a[mi][2], a[mi][3], bf[nb][0], bf[nb][2]);
                mma_f16(acc[mi][nb*2+1][0], acc[mi][nb*2+1][1], acc[mi][nb*2+1][2], acc[mi][nb*2+1][3],
                        a[mi][0], a[mi][1], a[mi][2], a[mi][3], bf[nb][1], bf[nb][3]);
            }
        }
    }

    const int qrow = ctx.lane >> 2;
    const int qcol = (ctx.lane & 3) << 1;

    #pragma unroll
    for (int mi = 0; mi < 2; ++mi) {
        const int r0 = rowBase + ctx.wm * 32 + mi * 16 + qrow;
        const int r1 = r0 + 8;
        const float d0 = (r0 < ctx.N) ? ctx.deg[r0] : 0.f;
        const float d1 = (r1 < ctx.N) ? ctx.deg[r1] : 0.f;
        #pragma unroll
        for (int ni = 0; ni < 8; ++ni) {
            const int c = ctx.wn * 64 + ni * 8 + qcol;
            const float b0v = ctx.sb[c], b1v = ctx.sb[c + 1];
            if (r0 < ctx.N) {
                float2 o;
                o.x = tanh_fast(acc[mi][ni][0] + d0 * b0v);
                o.y = tanh_fast(acc[mi][ni][1] + d0 * b1v);
                *reinterpret_cast<float2*>(&ctx.out[(size_t)r0 * D + c]) = o;
            }
            if (r1 < ctx.N) {
                float2 o;
                o.x = tanh_fast(acc[mi][ni][2] + d1 * b0v);
                o.y = tanh_fast(acc[mi][ni][3] + d1 * b1v);
                *reinterpret_cast<float2*>(&ctx.out[(size_t)r1 * D + c]) = o;
            }
        }
    }
}

__global__ __launch_bounds__(256, 2) void gemm_mma_kernel(
    const __half* __restrict__ agg,
    const __half* __restrict__ W_h,
    const float* __restrict__ b,
    const float* __restrict__ deg,
    float* __restrict__ out,
    int N, int nTiles)
{
    extern __shared__ char smem[];
    float* sb = reinterpret_cast<float*>(smem + SM_BV);

    const int tid  = threadIdx.x;
    const int wid  = tid >> 5;
    const int lane = tid & 31;

    const int tile0 = blockIdx.x;
    const int tile1 = blockIdx.x + gridDim.x;
    const int rowBase0 = tile0 * 128;
    const int rowBase1 = tile1 * 128;

    if (tid < 128) sb[tid] = b[tid];

    const uint32_t sB  = smem_u32(smem + SM_B);
    const uint32_t sA0 = smem_u32(smem + SM_A0);
    const uint32_t sA1 = smem_u32(smem + SM_A1);

    #pragma unroll
    for (int it = 0; it < 8; ++it) {
        const int i = tid + it * 256;
        const int r = i >> 4;
        const int c = i & 15;
        cp16(sB  + r * (LDH * 2) + c * 16, W_h + (size_t)r * D + c * 8);
        cp16(sA0 + r * (LDH * 2) + c * 16,
             agg + (size_t)(rowBase0 + r) * D + c * 8);
    }
    cp_commit();

    if (tile1 < nTiles) {
        #pragma unroll
        for (int it = 0; it < 8; ++it) {
            const int i = tid + it * 256;
            const int r = i >> 4;
            const int c = i & 15;
            cp16(sA1 + r * (LDH * 2) + c * 16,
                 agg + (size_t)(rowBase1 + r) * D + c * 8);
        }
    }
    cp_commit();   // group committed even if empty: keeps wait<1> semantics

    GemmCtx ctx;
    ctx.deg = deg; ctx.out = out; ctx.sb = sb; ctx.N = N;
    ctx.wm = wid & 3; ctx.wn = wid >> 2; ctx.lane = lane; ctx.sB = sB;

    cp_wait<1>();
    __syncthreads();
    compute_tile(ctx, sA0, rowBase0);

    if (tile1 < nTiles) {
        cp_wait<0>();
        __syncthreads();
        compute_tile(ctx, sA1, rowBase1);
    }
}

// ===========================================================================
extern "C" void kernel_launch(void* const* d_in, const int* in_sizes, int n_in,
                              void* d_out, int out_size)
{
    const float* input   = (const float*)d_in[0];
    const float* W       = (const float*)d_in[1];
    const float* b       = (const float*)d_in[2];
    const int*   adj_row = (const int*)d_in[3];
    const int*   adj_col = (const int*)d_in[4];
    const float* adj_val = (const float*)d_in[5];
    float* out = (float*)d_out;

    const int N = in_sizes[0] / D;
    const int E = in_sizes[3];

    __half *inhPtr = nullptr, *whPtr = nullptr, *agghPtr = nullptr;
    float *degPtr = nullptr;
    cudaGetSymbolAddress((void**)&inhPtr, g_in_h);
    cudaGetSymbolAddress((void**)&whPtr, g_W_h);
    cudaGetSymbolAddress((void**)&agghPtr, g_agg_h);
    cudaGetSymbolAddress((void**)&degPtr, g_deg);

    // Fused prep: convert input/W to fp16 + zero agg/deg (round-6 shape)
    const int nInPairs = N * D / 8;
    const int nWPairs  = D * D / 8;
    const int nZero16  = N * D / 8;       // halves: N*D*2B / 16B
    const int nDeg4    = (N + 3) / 4;
    const int totalPrep = nInPairs + nWPairs + nZero16 + nDeg4;
    prep_kernel<<<(totalPrep + 255) / 256, 256>>>(
        input, W, inhPtr, whPtr, agghPtr, degPtr,
        nInPairs, nWPairs, nZero16, nDeg4);

    // Scatter: g_agg_h = A_sparse @ input (fp16), g_deg = rowsum(adj_val)
    const int nWarps = (E + EDGES_PER_WARP - 1) / EDGES_PER_WARP;
    const int scatterBlocks = (nWarps * 32 + 255) / 256;
    scatter_kernel<<<scatterBlocks, 256>>>(adj_row, adj_col, adj_val,
                                           inhPtr, agghPtr, degPtr, E);

    // Persistent tensor-core GEMM + fused bias/tanh epilogue
    // (grid = min(nTiles, 2*SMs): balanced 2 CTAs/SM)
    cudaFuncSetAttribute(gemm_mma_kernel,
                         cudaFuncAttributeMaxDynamicSharedMemorySize,
                         GEMM_SMEM_TOTAL);
    int sms = 148;
    cudaDeviceGetAttribute(&sms, cudaDevAttrMultiProcessorCount, 0);
    const int nTiles = (N + 127) / 128;
    int gemmBlocks = 2 * sms;
    if (gemmBlocks > nTiles) gemmBlocks = nTiles;
    gemm_mma_kernel<<<gemmBlocks, 256, GEMM_SMEM_TOTAL>>>(
        agghPtr, whPtr, b, degPtr, out, N, nTiles);
}

// round 17
// speedup vs baseline: 1.5408x; 1.4915x over previous
#include <cuda_runtime.h>
#include <cuda_fp16.h>
#include <cstdint>

#define D 128
#define MAX_N 50000
#define MAX_N_PAD 50176          // padded: GEMM tiles may over-read safely
#define EDGES_PER_WARP 64

// ===========================================================================
// Static scratch (no allocations allowed)
// ===========================================================================
__device__ __align__(256) __half g_in_h[(size_t)MAX_N * D];       // fp16 input
__device__ __align__(256) __half g_W_h[D * D];                    // fp16 W
__device__ __align__(256) __half g_agg_h[(size_t)MAX_N_PAD * D];  // fp16 agg
__device__ __align__(256) float g_deg[MAX_N];                     // rowsum(adj_val)

// ===========================================================================
// Kernel 0: fused prep — convert input/W to fp16 AND zero agg/deg.
// ===========================================================================
__global__ __launch_bounds__(256) void prep_kernel(
    const float* __restrict__ input,
    const float* __restrict__ W,
    __half* __restrict__ in_h,
    __half* __restrict__ W_h,
    __half* __restrict__ agg,
    float* __restrict__ deg,
    int nInPairs, int nWPairs, int nZero16, int nDeg4)
{
    const int i = blockIdx.x * blockDim.x + threadIdx.x;

    if (i < nInPairs) {
        const float4 v0 = reinterpret_cast<const float4*>(input)[i * 2];
        const float4 v1 = reinterpret_cast<const float4*>(input)[i * 2 + 1];
        __half2 h0 = __floats2half2_rn(v0.x, v0.y);
        __half2 h1 = __floats2half2_rn(v0.z, v0.w);
        __half2 h2 = __floats2half2_rn(v1.x, v1.y);
        __half2 h3 = __floats2half2_rn(v1.z, v1.w);
        uint4 u;
        u.x = *reinterpret_cast<uint32_t*>(&h0);
        u.y = *reinterpret_cast<uint32_t*>(&h1);
        u.z = *reinterpret_cast<uint32_t*>(&h2);
        u.w = *reinterpret_cast<uint32_t*>(&h3);
        reinterpret_cast<uint4*>(in_h)[i] = u;
        return;
    }
    int j = i - nInPairs;
    if (j < nWPairs) {
        const float4 v0 = reinterpret_cast<const float4*>(W)[j * 2];
        const float4 v1 = reinterpret_cast<const float4*>(W)[j * 2 + 1];
        __half2 h0 = __floats2half2_rn(v0.x, v0.y);
        __half2 h1 = __floats2half2_rn(v0.z, v0.w);
        __half2 h2 = __floats2half2_rn(v1.x, v1.y);
        __half2 h3 = __floats2half2_rn(v1.z, v1.w);
        uint4 u;
        u.x = *reinterpret_cast<uint32_t*>(&h0);
        u.y = *reinterpret_cast<uint32_t*>(&h1);
        u.z = *reinterpret_cast<uint32_t*>(&h2);
        u.w = *reinterpret_cast<uint32_t*>(&h3);
        reinterpret_cast<uint4*>(W_h)[j] = u;
        return;
    }
    j -= nWPairs;
    if (j < nZero16) {
        reinterpret_cast<uint4*>(agg)[j] = make_uint4(0, 0, 0, 0);
        return;
    }
    j -= nZero16;
    if (j < nDeg4)
        reinterpret_cast<uint4*>(deg)[j] = make_uint4(0, 0, 0, 0);
}

// ===========================================================================
// Kernel 1: COO scatter on fp16 input, fp32 register accumulation:
//   g_agg_h[r] += val * in_h[c]  (fp16 store),  g_deg[r] += val
// Sorted rows -> register-run accumulation; plain stores for interior rows,
// atomics only at chunk boundaries.
// ===========================================================================
__device__ __forceinline__ void flush_row(__half* __restrict__ agg,
                                          float* __restrict__ deg,
                                          int curRow, int lane,
                                          const float4& acc, float degAcc,
                                          int firstRow, bool isFinal)
{
    if (curRow < 0) return;
    __half2 h0 = __floats2half2_rn(acc.x, acc.y);
    __half2 h1 = __floats2half2_rn(acc.z, acc.w);
    __half2* p = reinterpret_cast<__half2*>(agg + (size_t)curRow * D + lane * 4);
    if (curRow == firstRow || isFinal) {
        atomicAdd(p + 0, h0);
        atomicAdd(p + 1, h1);
        if (lane == 0) atomicAdd(&deg[curRow], degAcc);
    } else {
        uint2 u = make_uint2(*reinterpret_cast<uint32_t*>(&h0),
                             *reinterpret_cast<uint32_t*>(&h1));
        *reinterpret_cast<uint2*>(p) = u;
        if (lane == 0) deg[curRow] = degAcc;
    }
}

__global__ __launch_bounds__(256) void scatter_kernel(
    const int* __restrict__ adj_row,
    const int* __restrict__ adj_col,
    const float* __restrict__ adj_val,
    const __half* __restrict__ in_h,
    __half* __restrict__ agg,
    float* __restrict__ deg,
    int E)
{
    const int warpId = (blockIdx.x * blockDim.x + threadIdx.x) >> 5;
    const int lane = threadIdx.x & 31;
    const int base = warpId * EDGES_PER_WARP;
    if (base >= E) return;

    const int firstRow = adj_row[base];
    int curRow = -1;
    float4 acc = make_float4(0.f, 0.f, 0.f, 0.f);
    float degAcc = 0.f;

    for (int t = 0; t < EDGES_PER_WARP; t += 32) {
        const int e = base + t + lane;
        int r = -2, c = 0;
        float v = 0.f;
        if (e < E) { r = adj_row[e]; c = adj_col[e]; v = adj_val[e]; }

        #pragma unroll
        for (int j = 0; j < 32; ++j) {
            const int   rj = __shfl_sync(0xFFFFFFFFu, r, j);
            const int   cj = __shfl_sync(0xFFFFFFFFu, c, j);
            const float vj = __shfl_sync(0xFFFFFFFFu, v, j);
            if (rj < 0) break;
            if (rj != curRow) {
                flush_row(agg, deg, curRow, lane, acc, degAcc, firstRow, false);
                curRow = rj;
                acc = make_float4(0.f, 0.f, 0.f, 0.f);
                degAcc = 0.f;
            }
            const uint2 sv = *reinterpret_cast<const uint2*>(
                in_h + (size_t)cj * D + lane * 4);
            const float2 f0 = __half22float2(*reinterpret_cast<const __half2*>(&sv.x));
            const float2 f1 = __half22float2(*reinterpret_cast<const __half2*>(&sv.y));
            acc.x += vj * f0.x;
            acc.y += vj * f0.y;
            acc.z += vj * f1.x;
            acc.w += vj * f1.y;
            degAcc += vj;
        }
    }
    flush_row(agg, deg, curRow, lane, acc, degAcc, firstRow, true);
}

// ===========================================================================
// mma.sync / ldmatrix / cp.async helpers
// ===========================================================================
__device__ __forceinline__ void ldmx4(uint32_t& r0, uint32_t& r1,
                                      uint32_t& r2, uint32_t& r3,
                                      uint32_t saddr)
{
    asm volatile("ldmatrix.sync.aligned.m8n8.x4.shared.b16 {%0,%1,%2,%3}, [%4];"
                 : "=r"(r0), "=r"(r1), "=r"(r2), "=r"(r3) : "r"(saddr));
}
__device__ __forceinline__ void mma_f16(float& c0, float& c1, float& c2, float& c3,
                                        uint32_t a0, uint32_t a1, uint32_t a2, uint32_t a3,
                                        uint32_t b0, uint32_t b1)
{
    asm volatile(
        "mma.sync.aligned.m16n8k16.row.col.f32.f16.f16.f32 "
        "{%0,%1,%2,%3}, {%4,%5,%6,%7}, {%8,%9}, {%0,%1,%2,%3};"
        : "+f"(c0), "+f"(c1), "+f"(c2), "+f"(c3)
        : "r"(a0), "r"(a1), "r"(a2), "r"(a3), "r"(b0), "r"(b1));
}
__device__ __forceinline__ uint32_t smem_u32(const void* p) {
    return (uint32_t)__cvta_generic_to_shared(p);
}
__device__ __forceinline__ void cp16(uint32_t dst, const void* src) {
    asm volatile("cp.async.cg.shared.global [%0], [%1], 16;" :: "r"(dst), "l"(src));
}
__device__ __forceinline__ void cp_commit() {
    asm volatile("cp.async.commit_group;");
}
template <int NWAIT>
__device__ __forceinline__ void cp_wait() {
    asm volatile("cp.async.wait_group %0;" :: "n"(NWAIT));
}

// ===========================================================================
// Kernel 2: persistent fp16 tensor-core GEMM + fused epilogue.
// Grid = min(nTiles, 2*SMs): every SM hosts 2 CTAs, balanced 2-3 tiles/SM.
// CTA i does tiles {i, i+gridDim.x}; W loaded once, A double-buffered.
// ===========================================================================
#define LDH 136
#define TILE_BYTES_H (128 * LDH * 2)
#define SM_BV 0
#define SM_B  1024
#define SM_A0 (SM_B + TILE_BYTES_H)
#define SM_A1 (SM_A0 + TILE_BYTES_H)
#define GEMM_SMEM_TOTAL (SM_A1 + TILE_BYTES_H)   // 105472 B

struct GemmCtx {
    const float* deg;
    float* out;
    const float* sb;
    int N, wm, wn, lane;
    uint32_t sB;
};

__device__ __forceinline__ void compute_tile(const GemmCtx& ctx, uint32_t sA,
                                             int rowBase)
{
    float acc[2][8][4];
    #pragma unroll
    for (int mi = 0; mi < 2; ++mi)
        #pragma unroll
        for (int ni = 0; ni < 8; ++ni)
            #pragma unroll
            for (int q = 0; q < 4; ++q)
                acc[mi][ni][q] = 0.f;

    const int lrow = ctx.lane & 15;
    const int lkof = (ctx.lane >> 4) << 3;

    #pragma unroll
    for (int ks = 0; ks < 8; ++ks) {
        const uint32_t kb = (uint32_t)(ks * 16 + lkof) * 2;

        uint32_t a[2][4];
        #pragma unroll
        for (int mi = 0; mi < 2; ++mi) {
            uint32_t ra = (uint32_t)((ctx.wm * 32 + mi * 16 + lrow) * LDH) * 2 + kb;
            ldmx4(a[mi][0], a[mi][1], a[mi][2], a[mi][3], sA + ra);
        }
        uint32_t bf[4][4];
        #pragma unroll
        for (int nb = 0; nb < 4; ++nb) {
            uint32_t rb = (uint32_t)((ctx.wn * 64 + nb * 16 + lrow) * LDH) * 2 + kb;
            ldmx4(bf[nb][0], bf[nb][1], bf[nb][2], bf[nb][3], ctx.sB + rb);
        }
        #pragma unroll
        for (int mi = 0; mi < 2; ++mi) {
            #pragma unroll
            for (int nb = 0; nb < 4; ++nb) {
                mma_f16(acc[mi][nb*2][0], acc[mi][nb*2][1], acc[mi][nb*2][2], acc[mi][nb*2][3],
                        a[mi][0], a[mi][1], a[mi][2], a[mi][3], bf[nb][0], bf[nb][2]);
                mma_f16(acc[mi][nb*2+1][0], acc[mi][nb*2+1][1], acc[mi][nb*2+1][2], acc[mi][nb*2+1][3],
                        a[mi][0], a[mi][1], a[mi][2], a[mi][3], bf[nb][1], bf[nb][3]);
            }
        }
    }

    const int qrow = ctx.lane >> 2;
    const int qcol = (ctx.lane & 3) << 1;

    #pragma unroll
    for (int mi = 0; mi < 2; ++mi) {
        const int r0 = rowBase + ctx.wm * 32 + mi * 16 + qrow;
        const int r1 = r0 + 8;
        const float d0 = (r0 < ctx.N) ? ctx.deg[r0] : 0.f;
        const float d1 = (r1 < ctx.N) ? ctx.deg[r1] : 0.f;
        #pragma unroll
        for (int ni = 0; ni < 8; ++ni) {
            const int c = ctx.wn * 64 + ni * 8 + qcol;
            const float b0v = ctx.sb[c], b1v = ctx.sb[c + 1];
            if (r0 < ctx.N) {
                float2 o;
                o.x = tanhf(acc[mi][ni][0] + d0 * b0v);
                o.y = tanhf(acc[mi][ni][1] + d0 * b1v);
                *reinterpret_cast<float2*>(&ctx.out[(size_t)r0 * D + c]) = o;
            }
            if (r1 < ctx.N) {
                float2 o;
                o.x = tanhf(acc[mi][ni][2] + d1 * b0v);
                o.y = tanhf(acc[mi][ni][3] + d1 * b1v);
                *reinterpret_cast<float2*>(&ctx.out[(size_t)r1 * D + c]) = o;
            }
        }
    }
}

__global__ __launch_bounds__(256, 2) void gemm_mma_kernel(
    const __half* __restrict__ agg,
    const __half* __restrict__ W_h,
    const float* __restrict__ b,
    const float* __restrict__ deg,
    float* __restrict__ out,
    int N, int nTiles)
{
    extern __shared__ char smem[];
    float* sb = reinterpret_cast<float*>(smem + SM_BV);

    const int tid  = threadIdx.x;
    const int wid  = tid >> 5;
    const int lane = tid & 31;

    const int tile0 = blockIdx.x;
    const int tile1 = blockIdx.x + gridDim.x;
    const int rowBase0 = tile0 * 128;
    const int rowBase1 = tile1 * 128;

    if (tid < 128) sb[tid] = b[tid];

    const uint32_t sB  = smem_u32(smem + SM_B);
    const uint32_t sA0 = smem_u32(smem + SM_A0);
    const uint32_t sA1 = smem_u32(smem + SM_A1);

    #pragma unroll
    for (int it = 0; it < 8; ++it) {
        const int i = tid + it * 256;
        const int r = i >> 4;
        const int c = i & 15;
        cp16(sB  + r * (LDH * 2) + c * 16, W_h + (size_t)r * D + c * 8);
        cp16(sA0 + r * (LDH * 2) + c * 16,
             agg + (size_t)(rowBase0 + r) * D + c * 8);
    }
    cp_commit();

    if (tile1 < nTiles) {
        #pragma unroll
        for (int it = 0; it < 8; ++it) {
            const int i = tid + it * 256;
            const int r = i >> 4;
            const int c = i & 15;
            cp16(sA1 + r * (LDH * 2) + c * 16,
                 agg + (size_t)(rowBase1 + r) * D + c * 8);
        }
    }
    cp_commit();   // group committed even if empty: keeps wait<1> semantics

    GemmCtx ctx;
    ctx.deg = deg; ctx.out = out; ctx.sb = sb; ctx.N = N;
    ctx.wm = wid & 3; ctx.wn = wid >> 2; ctx.lane = lane; ctx.sB = sB;

    cp_wait<1>();
    __syncthreads();
    compute_tile(ctx, sA0, rowBase0);

    if (tile1 < nTiles) {
        cp_wait<0>();
        __syncthreads();
        compute_tile(ctx, sA1, rowBase1);
    }
}

// ===========================================================================
extern "C" void kernel_launch(void* const* d_in, const int* in_sizes, int n_in,
                              void* d_out, int out_size)
{
    const float* input   = (const float*)d_in[0];
    const float* W       = (const float*)d_in[1];
    const float* b       = (const float*)d_in[2];
    const int*   adj_row = (const int*)d_in[3];
    const int*   adj_col = (const int*)d_in[4];
    const float* adj_val = (const float*)d_in[5];
    float* out = (float*)d_out;

    const int N = in_sizes[0] / D;
    const int E = in_sizes[3];

    __half *inhPtr = nullptr, *whPtr = nullptr, *agghPtr = nullptr;
    float *degPtr = nullptr;
    cudaGetSymbolAddress((void**)&inhPtr, g_in_h);
    cudaGetSymbolAddress((void**)&whPtr, g_W_h);
    cudaGetSymbolAddress((void**)&agghPtr, g_agg_h);
    cudaGetSymbolAddress((void**)&degPtr, g_deg);

    // Fused prep: convert input/W to fp16 + zero agg/deg
    const int nInPairs = N * D / 8;
    const int nWPairs  = D * D / 8;
    const int nZero16  = N * D / 8;       // halves: N*D*2B / 16B
    const int nDeg4    = (N + 3) / 4;
    const int totalPrep = nInPairs + nWPairs + nZero16 + nDeg4;
    prep_kernel<<<(totalPrep + 255) / 256, 256>>>(
        input, W, inhPtr, whPtr, agghPtr, degPtr,
        nInPairs, nWPairs, nZero16, nDeg4);

    // Scatter: g_agg_h = A_sparse @ input (fp16), g_deg = rowsum(adj_val)
    const int nWarps = (E + EDGES_PER_WARP - 1) / EDGES_PER_WARP;
    const int scatterBlocks = (nWarps * 32 + 255) / 256;
    scatter_kernel<<<scatterBlocks, 256>>>(adj_row, adj_col, adj_val,
                                           inhPtr, agghPtr, degPtr, E);

    // Persistent tensor-core GEMM + fused bias/tanh epilogue.
    // Grid = min(nTiles, 2*SMs): balanced 2 CTAs/SM, makespan 3 tiles.
    cudaFuncSetAttribute(gemm_mma_kernel,
                         cudaFuncAttributeMaxDynamicSharedMemorySize,
                         GEMM_SMEM_TOTAL);
    int sms = 148;
    cudaDeviceGetAttribute(&sms, cudaDevAttrMultiProcessorCount, 0);
    const int nTiles = (N + 127) / 128;
    int gemmBlocks = 2 * sms;
    if (gemmBlocks > nTiles) gemmBlocks = nTiles;
    gemm_mma_kernel<<<gemmBlocks, 256, GEMM_SMEM_TOTAL>>>(
        agghPtr, whPtr, b, degPtr, out, N, nTiles);
}